// round 11
// baseline (speedup 1.0000x reference)
#include <cuda_runtime.h>

// Problem constants (dataset-fixed shapes; margins included).
#define MAXN 50048
#define MAXE 1000000

// Scratch (module-level device arrays; 16B-aligned for vector access).
__device__ __align__(16) int   g_cnt[MAXN];          // in-degree counts
__device__ __align__(16) int   g_off[MAXN];          // CSR offsets (exclusive scan)
__device__ __align__(16) int   g_cursor[MAXN];       // fill cursors
__device__ __align__(16) int   g_partial[256];       // scan partials
__device__ __align__(16) int   g_csr_src[MAXE];      // CSR adjacency (src per dst)
__device__ __align__(16) float g_dinv[MAXN];         // 1/sqrt(deg)
__device__ __align__(16) float g_y[MAXN * 96];       // dinv-scaled activations Y
__device__ __align__(16) float g_agg[MAXN * 96];     // aggregated features Z
__device__ __align__(16) float g_bufA[MAXN * 256];   // activation ping
__device__ __align__(16) float g_bufB[MAXN * 256];   // activation pong

// ---------------------------------------------------------------------------
// CSR build: count -> scan -> fill.  edge_index is int32 (JAX x64 disabled).
// ---------------------------------------------------------------------------
__global__ void zero_cnt_kernel(int* __restrict__ cnt, int n) {
    int i = blockIdx.x * blockDim.x + threadIdx.x;
    if (i < n) cnt[i] = 0;
}

__global__ void count_kernel(const int* __restrict__ ei, int E,
                             int* __restrict__ cnt) {
    int e = blockIdx.x * blockDim.x + threadIdx.x;
    if (e < E) atomicAdd(&cnt[ei[E + e]], 1);  // row 1 = dst
}

// Block-level exclusive scan, 1024 elems/block (Hillis-Steele).
__global__ void scan1_kernel(const int* __restrict__ cnt, int n,
                             int* __restrict__ off, int* __restrict__ partial) {
    __shared__ int sm[1024];
    int t = threadIdx.x;
    int i = blockIdx.x * 1024 + t;
    int v = (i < n) ? cnt[i] : 0;
    sm[t] = v;
    __syncthreads();
#pragma unroll
    for (int ofs = 1; ofs < 1024; ofs <<= 1) {
        int add = (t >= ofs) ? sm[t - ofs] : 0;
        __syncthreads();
        sm[t] += add;
        __syncthreads();
    }
    if (i < n) off[i] = sm[t] - v;  // exclusive
    if (t == 1023) partial[blockIdx.x] = sm[t];
}

__global__ void scan2_kernel(int* __restrict__ partial, int nb) {
    __shared__ int sm[256];
    int t = threadIdx.x;
    int v = (t < nb) ? partial[t] : 0;
    sm[t] = v;
    __syncthreads();
#pragma unroll
    for (int ofs = 1; ofs < 256; ofs <<= 1) {
        int add = (t >= ofs) ? sm[t - ofs] : 0;
        __syncthreads();
        sm[t] += add;
        __syncthreads();
    }
    if (t < nb) partial[t] = sm[t] - v;  // exclusive
}

// Finalize offsets + cursors + dinv in one pass.
__global__ void scan3_kernel(int* __restrict__ off, const int* __restrict__ partial,
                             int* __restrict__ cursor, const int* __restrict__ cnt,
                             float* __restrict__ dinv, int n) {
    int i = blockIdx.x * blockDim.x + threadIdx.x;
    if (i < n) {
        int o = off[i] + partial[i >> 10];
        off[i] = o;
        cursor[i] = o;
        dinv[i] = rsqrtf(1.0f + (float)cnt[i]);  // +1 self loop
    }
}

__global__ void fill_kernel(const int* __restrict__ ei, int E,
                            int* __restrict__ cursor, int* __restrict__ csr_src) {
    int e = blockIdx.x * blockDim.x + threadIdx.x;
    if (e < E) {
        int s = ei[e];
        int d = ei[E + e];
        int pos = atomicAdd(&cursor[d], 1);
        csr_src[pos] = s;
    }
}

// ---------------------------------------------------------------------------
// Y = dinv ⊙ X  (row scale), thread per (node, 4 channels).
// ---------------------------------------------------------------------------
template <int C4>
__global__ void scale_kernel(const float* __restrict__ X,
                             const float* __restrict__ dinv,
                             float* __restrict__ Y, int n) {
    int idx = blockIdx.x * blockDim.x + threadIdx.x;
    if (idx >= n * C4) return;
    int node = idx / C4;
    float d = dinv[node];
    float4 x = reinterpret_cast<const float4*>(X)[idx];
    reinterpret_cast<float4*>(Y)[idx] =
        make_float4(x.x * d, x.y * d, x.z * d, x.w * d);
}

// ---------------------------------------------------------------------------
// Aggregation on pre-scaled Y: Z[v] = dinv[v] * (Y[v] + sum_{u in N(v)} Y[u]).
// Thread per (node, 8 channels). Pure adds in the loop — no dinv gather.
// ---------------------------------------------------------------------------
template <int C8>  // channels/8
__global__ void __launch_bounds__(256)
agg_kernel(const int* __restrict__ off, const int* __restrict__ cnt,
           const int* __restrict__ csr_src, const float* __restrict__ dinv,
           const float* __restrict__ Y, float* __restrict__ Z, int n) {
    int idx = blockIdx.x * blockDim.x + threadIdx.x;
    int node = idx / C8;
    int c8 = idx - node * C8;
    if (node >= n) return;

    const float4* Y4 = reinterpret_cast<const float4*>(Y);
    const size_t S4 = C8 * 2;  // float4 stride per row
    size_t base = (size_t)node * S4 + c8 * 2;
    float4 acc0 = __ldg(Y4 + base);
    float4 acc1 = __ldg(Y4 + base + 1);

    int start = off[node];
    int deg = cnt[node];
    const int* cp = csr_src + start;

    int j = 0;
    for (; j + 4 <= deg; j += 4) {
        int s0 = __ldg(cp + j);
        int s1 = __ldg(cp + j + 1);
        int s2 = __ldg(cp + j + 2);
        int s3 = __ldg(cp + j + 3);
        size_t b0 = (size_t)s0 * S4 + c8 * 2;
        size_t b1 = (size_t)s1 * S4 + c8 * 2;
        size_t b2 = (size_t)s2 * S4 + c8 * 2;
        size_t b3 = (size_t)s3 * S4 + c8 * 2;
        float4 p00 = __ldg(Y4 + b0), p01 = __ldg(Y4 + b0 + 1);
        float4 p10 = __ldg(Y4 + b1), p11 = __ldg(Y4 + b1 + 1);
        float4 p20 = __ldg(Y4 + b2), p21 = __ldg(Y4 + b2 + 1);
        float4 p30 = __ldg(Y4 + b3), p31 = __ldg(Y4 + b3 + 1);
        acc0.x += p00.x; acc0.y += p00.y; acc0.z += p00.z; acc0.w += p00.w;
        acc1.x += p01.x; acc1.y += p01.y; acc1.z += p01.z; acc1.w += p01.w;
        acc0.x += p10.x; acc0.y += p10.y; acc0.z += p10.z; acc0.w += p10.w;
        acc1.x += p11.x; acc1.y += p11.y; acc1.z += p11.z; acc1.w += p11.w;
        acc0.x += p20.x; acc0.y += p20.y; acc0.z += p20.z; acc0.w += p20.w;
        acc1.x += p21.x; acc1.y += p21.y; acc1.z += p21.z; acc1.w += p21.w;
        acc0.x += p30.x; acc0.y += p30.y; acc0.z += p30.z; acc0.w += p30.w;
        acc1.x += p31.x; acc1.y += p31.y; acc1.z += p31.z; acc1.w += p31.w;
    }
    for (; j < deg; j++) {
        int s = __ldg(cp + j);
        size_t b = (size_t)s * S4 + c8 * 2;
        float4 p0 = __ldg(Y4 + b), p1 = __ldg(Y4 + b + 1);
        acc0.x += p0.x; acc0.y += p0.y; acc0.z += p0.z; acc0.w += p0.w;
        acc1.x += p1.x; acc1.y += p1.y; acc1.z += p1.z; acc1.w += p1.w;
    }

    float d = dinv[node];
    float4* Z4 = reinterpret_cast<float4*>(Z);
    Z4[base] = make_float4(acc0.x * d, acc0.y * d, acc0.z * d, acc0.w * d);
    Z4[base + 1] = make_float4(acc1.x * d, acc1.y * d, acc1.z * d, acc1.w * d);
}

// ---------------------------------------------------------------------------
// GEMM: C[n,K] = A[n,M] @ W[M,K]. Register-blocked 8 nodes x 4 cols per
// thread, packed fma.rn.f32x2 (2 FP32 FMA per fma-pipe issue).
// EPI: 0 none, 1 bias+relu, 2 bias, 3 bias+BN(eval)+relu,
//      4 bias+BN(eval)+relu then *dinv[node] (pre-scale for next aggregation).
// ---------------------------------------------------------------------------
template <int M, int K, int EPI>
__global__ void __launch_bounds__(256)
gemm8_kernel(const float* __restrict__ A, const float* __restrict__ W,
             const float* __restrict__ bias, const float* __restrict__ gamma,
             const float* __restrict__ beta, const float* __restrict__ dinv,
             float* __restrict__ C, int n) {
    constexpr int KC = K / 4;
    constexpr int MS = M / 4;
    int idx = blockIdx.x * blockDim.x + threadIdx.x;
    int ng = idx / KC;
    int c4 = idx - ng * KC;
    int n0 = ng * 8;
    if (n0 >= n) return;

    int ni[8];
#pragma unroll
    for (int i = 0; i < 8; i++) ni[i] = (n0 + i < n) ? (n0 + i) : n0;

    const float4* A4 = reinterpret_cast<const float4*>(A);
    unsigned long long acc[8][2] = {};  // 8 nodes x (2 packed f32x2 = 4 cols)

#pragma unroll
    for (int m4 = 0; m4 < MS; m4++) {
        float4 a[8];
#pragma unroll
        for (int i = 0; i < 8; i++)
            a[i] = __ldg(A4 + (size_t)ni[i] * MS + m4);
        const ulonglong2* wp =
            reinterpret_cast<const ulonglong2*>(W + (size_t)(m4 * 4) * K) + c4;
#pragma unroll
        for (int r = 0; r < 4; r++) {
            ulonglong2 w = wp[r * KC];
#pragma unroll
            for (int i = 0; i < 8; i++) {
                float av = r == 0 ? a[i].x : r == 1 ? a[i].y : r == 2 ? a[i].z : a[i].w;
                unsigned long long p;
                asm("mov.b64 %0, {%1,%1};" : "=l"(p) : "f"(av));
                asm("fma.rn.f32x2 %0, %1, %2, %0;" : "+l"(acc[i][0]) : "l"(p), "l"(w.x));
                asm("fma.rn.f32x2 %0, %1, %2, %0;" : "+l"(acc[i][1]) : "l"(p), "l"(w.y));
            }
        }
    }

    float4 bv = make_float4(0.f, 0.f, 0.f, 0.f);
    float4 gs = make_float4(0.f, 0.f, 0.f, 0.f);
    float4 bev = make_float4(0.f, 0.f, 0.f, 0.f);
    if (EPI != 0) bv = reinterpret_cast<const float4*>(bias)[c4];
    if (EPI >= 3) {
        const float INV = 0.99999500003749971f;  // 1/sqrt(1+1e-5)
        float4 gv = reinterpret_cast<const float4*>(gamma)[c4];
        gs = make_float4(gv.x * INV, gv.y * INV, gv.z * INV, gv.w * INV);
        bev = reinterpret_cast<const float4*>(beta)[c4];
    }

#pragma unroll
    for (int i = 0; i < 8; i++) {
        int node = n0 + i;
        if (node >= n) break;
        float2 lo = *reinterpret_cast<float2*>(&acc[i][0]);
        float2 hi = *reinterpret_cast<float2*>(&acc[i][1]);
        float4 o = make_float4(lo.x, lo.y, hi.x, hi.y);
        if (EPI == 1 || EPI == 2) {
            o.x += bv.x; o.y += bv.y; o.z += bv.z; o.w += bv.w;
            if (EPI == 1) {
                o.x = fmaxf(o.x, 0.f); o.y = fmaxf(o.y, 0.f);
                o.z = fmaxf(o.z, 0.f); o.w = fmaxf(o.w, 0.f);
            }
        } else if (EPI >= 3) {
            o.x = fmaxf(fmaf(o.x + bv.x, gs.x, bev.x), 0.f);
            o.y = fmaxf(fmaf(o.y + bv.y, gs.y, bev.y), 0.f);
            o.z = fmaxf(fmaf(o.z + bv.z, gs.z, bev.z), 0.f);
            o.w = fmaxf(fmaf(o.w + bv.w, gs.w, bev.w), 0.f);
            if (EPI == 4) {
                float d = dinv[node];
                o.x *= d; o.y *= d; o.z *= d; o.w *= d;
            }
        }
        reinterpret_cast<float4*>(C)[(size_t)node * KC + c4] = o;
    }
}

// ---------------------------------------------------------------------------
// Launch
// ---------------------------------------------------------------------------
static inline int grid_for(long long threads, int block) {
    return (int)((threads + block - 1) / block);
}

extern "C" void kernel_launch(void* const* d_in, const int* in_sizes, int n_in,
                              void* d_out, int out_size) {
    const float* x  = (const float*)d_in[0];
    const int*   ei = (const int*)d_in[1];   // int32
    const float* w1 = (const float*)d_in[2];
    const float* b1 = (const float*)d_in[3];
    const float* g1 = (const float*)d_in[4];
    const float* be1 = (const float*)d_in[5];
    const float* w2 = (const float*)d_in[6];
    const float* b2 = (const float*)d_in[7];
    const float* g2 = (const float*)d_in[8];
    const float* be2 = (const float*)d_in[9];
    const float* w3 = (const float*)d_in[10];
    const float* b3 = (const float*)d_in[11];
    const float* g3 = (const float*)d_in[12];
    const float* be3 = (const float*)d_in[13];
    const float* lw1 = (const float*)d_in[14];
    const float* lb1 = (const float*)d_in[15];
    const float* lw2 = (const float*)d_in[16];
    const float* lb2 = (const float*)d_in[17];
    const float* lw3 = (const float*)d_in[18];
    const float* lb3 = (const float*)d_in[19];
    const float* lw4 = (const float*)d_in[20];
    const float* lb4 = (const float*)d_in[21];
    float* out = (float*)d_out;

    const int N = in_sizes[0] / 64;
    const int E = in_sizes[1] / 2;

    int *cnt, *off, *cursor, *partial, *csr_src;
    float *dinv, *y, *agg, *bufA, *bufB;
    cudaGetSymbolAddress((void**)&cnt,     g_cnt);
    cudaGetSymbolAddress((void**)&off,     g_off);
    cudaGetSymbolAddress((void**)&cursor,  g_cursor);
    cudaGetSymbolAddress((void**)&partial, g_partial);
    cudaGetSymbolAddress((void**)&csr_src, g_csr_src);
    cudaGetSymbolAddress((void**)&dinv,    g_dinv);
    cudaGetSymbolAddress((void**)&y,       g_y);
    cudaGetSymbolAddress((void**)&agg,     g_agg);
    cudaGetSymbolAddress((void**)&bufA,    g_bufA);
    cudaGetSymbolAddress((void**)&bufB,    g_bufB);

    const int BLK = 256;
    const int nb = (N + 1023) / 1024;  // scan blocks (<=256)

    // --- CSR build + norms ---
    zero_cnt_kernel<<<grid_for(N, BLK), BLK>>>(cnt, N);
    count_kernel<<<grid_for(E, BLK), BLK>>>(ei, E, cnt);
    scan1_kernel<<<nb, 1024>>>(cnt, N, off, partial);
    scan2_kernel<<<1, 256>>>(partial, nb);
    scan3_kernel<<<grid_for(N, BLK), BLK>>>(off, partial, cursor, cnt, dinv, N);
    fill_kernel<<<grid_for(E, BLK), BLK>>>(ei, E, cursor, csr_src);

    const long long ngrp = (N + 7) / 8;

    // --- GCN layer 1: Y0 = dinv*x, Z1 = dinv*(sum Y0), H1 = relu(bn(Z1 W1)),
    //     output pre-scaled Y1 = dinv*H1 (EPI 4). x is 64ch.
    scale_kernel<16><<<grid_for((long long)N * 16, BLK), BLK>>>(x, dinv, y, N);
    agg_kernel<8><<<grid_for((long long)N * 8, BLK), BLK>>>(off, cnt, csr_src, dinv, y, agg, N);
    gemm8_kernel<64, 96, 4><<<grid_for(ngrp * 24, BLK), BLK>>>(agg, w1, b1, g1, be1, dinv, bufA, N);

    // --- GCN layer 2 (bufA holds Y1) ---
    agg_kernel<12><<<grid_for((long long)N * 12, BLK), BLK>>>(off, cnt, csr_src, dinv, bufA, agg, N);
    gemm8_kernel<96, 96, 4><<<grid_for(ngrp * 24, BLK), BLK>>>(agg, w2, b2, g2, be2, dinv, bufB, N);

    // --- GCN layer 3 (bufB holds Y2); plain BN+ReLU output (EPI 3) ---
    agg_kernel<12><<<grid_for((long long)N * 12, BLK), BLK>>>(off, cnt, csr_src, dinv, bufB, agg, N);
    gemm8_kernel<96, 96, 3><<<grid_for(ngrp * 24, BLK), BLK>>>(agg, w3, b3, g3, be3, nullptr, bufA, N);

    // --- MLP head ---
    gemm8_kernel<96, 256, 1><<<grid_for(ngrp * 64, BLK), BLK>>>(bufA, lw1, lb1, nullptr, nullptr, nullptr, bufB, N);
    gemm8_kernel<256, 128, 1><<<grid_for(ngrp * 32, BLK), BLK>>>(bufB, lw2, lb2, nullptr, nullptr, nullptr, bufA, N);
    gemm8_kernel<128, 64, 1><<<grid_for(ngrp * 16, BLK), BLK>>>(bufA, lw3, lb3, nullptr, nullptr, nullptr, bufB, N);
    gemm8_kernel<64, 8, 2><<<grid_for(ngrp * 2, BLK), BLK>>>(bufB, lw4, lb4, nullptr, nullptr, nullptr, out, N);
}